// round 2
// baseline (speedup 1.0000x reference)
#include <cuda_runtime.h>
#include <cstdint>

// Problem constants
#define NN   50000
#define EE   800000
#define NIN  128
#define NHID 256

#define SCAN_B  1024
#define SCAN_NB ((NN + SCAN_B - 1) / SCAN_B)   // 49

// ---------------- scratch (no allocations allowed) ----------------
__device__ int   g_is64;
__device__ int   g_deg[NN];
__device__ float g_dinv[NN];
__device__ int   g_ptr[NN + 1];
__device__ int   g_cur[NN];
__device__ int   g_src[EE];
__device__ int   g_bsum[SCAN_NB];
__device__ float g_h [(size_t)NN * NIN];    // aggregated features
__device__ float g_h1[(size_t)NN * NHID];   // after layer 1

// ---------------- edge-index dtype detection ----------------
// JAX with default x64-disabled config downcasts int64 -> int32. Detect which
// layout the harness actually gave us by sanity-checking int64 interpretation.
__global__ void k_detect(const void* __restrict__ ei) {
    if (threadIdx.x == 0) {
        const long long* p = (const long long*)ei;
        int ok = 1;
        for (int i = 0; i < 16; i++) {
            long long v = p[i];
            if (v < 0 || v >= NN) { ok = 0; break; }
        }
        g_is64 = ok;
    }
}

__device__ __forceinline__ int edge_at(const void* __restrict__ ei, long long idx) {
    if (g_is64) return (int)((const long long*)ei)[idx];
    return ((const int*)ei)[idx];
}

// ---------------- degree / normalization ----------------
__global__ void k_init() {
    int i = blockIdx.x * blockDim.x + threadIdx.x;
    if (i < NN) g_deg[i] = 1;   // self loop
}

__global__ void k_count(const void* __restrict__ ei) {
    int e = blockIdx.x * blockDim.x + threadIdx.x;
    if (e < EE) {
        int col = edge_at(ei, (long long)EE + e);
        atomicAdd(&g_deg[col], 1);
    }
}

__global__ void k_dinv() {
    int i = blockIdx.x * blockDim.x + threadIdx.x;
    if (i < NN) g_dinv[i] = rsqrtf((float)g_deg[i]);
}

// ---------------- exclusive scan of (deg-1) -> CSR row pointers ----------------
__global__ void k_scan1() {
    __shared__ int sh[SCAN_B];
    int gid = blockIdx.x * SCAN_B + threadIdx.x;
    int v = (gid < NN) ? (g_deg[gid] - 1) : 0;
    sh[threadIdx.x] = v;
    __syncthreads();
    for (int off = 1; off < SCAN_B; off <<= 1) {
        int t = (threadIdx.x >= off) ? sh[threadIdx.x - off] : 0;
        __syncthreads();
        sh[threadIdx.x] += t;
        __syncthreads();
    }
    if (gid < NN) g_ptr[gid] = sh[threadIdx.x] - v;   // exclusive within block
    if (threadIdx.x == SCAN_B - 1) g_bsum[blockIdx.x] = sh[SCAN_B - 1];
}

__global__ void k_scan2() {
    if (threadIdx.x == 0) {
        int acc = 0;
        for (int b = 0; b < SCAN_NB; b++) { int t = g_bsum[b]; g_bsum[b] = acc; acc += t; }
    }
}

__global__ void k_scan3() {
    int gid = blockIdx.x * SCAN_B + threadIdx.x;
    if (gid < NN) {
        int p = g_ptr[gid] + g_bsum[blockIdx.x];
        g_ptr[gid] = p;
        g_cur[gid] = p;
    }
    if (gid == 0) g_ptr[NN] = EE;
}

__global__ void k_fill(const void* __restrict__ ei) {
    int e = blockIdx.x * blockDim.x + threadIdx.x;
    if (e < EE) {
        int row = edge_at(ei, e);
        int col = edge_at(ei, (long long)EE + e);
        int pos = atomicAdd(&g_cur[col], 1);
        g_src[pos] = row;
    }
}

// ---------------- aggregation: warp per target node, gather-only ----------------
__global__ void __launch_bounds__(256) k_agg(const float* __restrict__ x) {
    int w = (blockIdx.x * blockDim.x + threadIdx.x) >> 5;
    int lane = threadIdx.x & 31;
    if (w >= NN) return;
    float di = g_dinv[w];
    const float4* __restrict__ x4 = (const float4*)x;
    float4 a = x4[(size_t)w * 32 + lane];           // self loop: dinv_i^2 * x[i]
    a.x *= di; a.y *= di; a.z *= di; a.w *= di;
    int s = g_ptr[w], e = g_ptr[w + 1];
    for (int k = s; k < e; k++) {
        int   j  = __ldg(&g_src[k]);
        float wj = __ldg(&g_dinv[j]);
        float4 v = x4[(size_t)j * 32 + lane];
        a.x = fmaf(wj, v.x, a.x);
        a.y = fmaf(wj, v.y, a.y);
        a.z = fmaf(wj, v.z, a.z);
        a.w = fmaf(wj, v.w, a.w);
    }
    a.x *= di; a.y *= di; a.z *= di; a.w *= di;
    ((float4*)g_h)[(size_t)w * 32 + lane] = a;
}

// ---------------- tiled fp32 GEMM + ReLU ----------------
#define BM 128
#define BN 128
#define BK 8
#define TM 8
#define TN 8

// C[M, NHID] = relu(g_h1[M, NHID] @ B) -> external C (layer 2)
template<int K>
__global__ void __launch_bounds__(256) gemm2_relu(const float* __restrict__ B,
                                                  float* __restrict__ C, int M) {
    const float* __restrict__ A = g_h1;
    __shared__ float As[BK][BM];
    __shared__ float Bs[BK][BN];

    int tid  = threadIdx.x;
    int brow = blockIdx.x * BM;
    int bcol = blockIdx.y * BN;
    int tx = tid & 15;       // 16 cols of threads
    int ty = tid >> 4;       // 16 rows of threads

    float acc[TM][TN];
    #pragma unroll
    for (int i = 0; i < TM; i++)
        #pragma unroll
        for (int j = 0; j < TN; j++) acc[i][j] = 0.f;

    int a_row = tid >> 1;
    int a_k   = (tid & 1) * 4;
    int b_k   = tid >> 5;
    int b_col = (tid & 31) * 4;

    for (int k0 = 0; k0 < K; k0 += BK) {
        float4 av = make_float4(0.f, 0.f, 0.f, 0.f);
        int grow = brow + a_row;
        if (grow < M) av = *(const float4*)(A + (size_t)grow * K + k0 + a_k);
        As[a_k + 0][a_row] = av.x;
        As[a_k + 1][a_row] = av.y;
        As[a_k + 2][a_row] = av.z;
        As[a_k + 3][a_row] = av.w;

        float4 bv = *(const float4*)(B + (size_t)(k0 + b_k) * NHID + bcol + b_col);
        *(float4*)&Bs[b_k][b_col] = bv;
        __syncthreads();

        #pragma unroll
        for (int kk = 0; kk < BK; kk++) {
            float ar[TM], br[TN];
            #pragma unroll
            for (int i = 0; i < TM; i++) ar[i] = As[kk][ty * TM + i];
            #pragma unroll
            for (int j = 0; j < TN; j++) br[j] = Bs[kk][tx * TN + j];
            #pragma unroll
            for (int i = 0; i < TM; i++)
                #pragma unroll
                for (int j = 0; j < TN; j++)
                    acc[i][j] = fmaf(ar[i], br[j], acc[i][j]);
        }
        __syncthreads();
    }

    #pragma unroll
    for (int i = 0; i < TM; i++) {
        int grow = brow + ty * TM + i;
        if (grow < M) {
            #pragma unroll
            for (int j = 0; j < TN; j += 4) {
                float4 v;
                v.x = fmaxf(acc[i][j + 0], 0.f);
                v.y = fmaxf(acc[i][j + 1], 0.f);
                v.z = fmaxf(acc[i][j + 2], 0.f);
                v.w = fmaxf(acc[i][j + 3], 0.f);
                *(float4*)(C + (size_t)grow * NHID + bcol + tx * TN + j) = v;
            }
        }
    }
}

// g_h1 = relu(g_h[M, NIN] @ B) (layer 1)
template<int K>
__global__ void __launch_bounds__(256) gemm1_relu(const float* __restrict__ B, int M) {
    const float* __restrict__ A = g_h;
    float* __restrict__ C = g_h1;
    __shared__ float As[BK][BM];
    __shared__ float Bs[BK][BN];

    int tid  = threadIdx.x;
    int brow = blockIdx.x * BM;
    int bcol = blockIdx.y * BN;
    int tx = tid & 15;
    int ty = tid >> 4;

    float acc[TM][TN];
    #pragma unroll
    for (int i = 0; i < TM; i++)
        #pragma unroll
        for (int j = 0; j < TN; j++) acc[i][j] = 0.f;

    int a_row = tid >> 1;
    int a_k   = (tid & 1) * 4;
    int b_k   = tid >> 5;
    int b_col = (tid & 31) * 4;

    for (int k0 = 0; k0 < K; k0 += BK) {
        float4 av = make_float4(0.f, 0.f, 0.f, 0.f);
        int grow = brow + a_row;
        if (grow < M) av = *(const float4*)(A + (size_t)grow * K + k0 + a_k);
        As[a_k + 0][a_row] = av.x;
        As[a_k + 1][a_row] = av.y;
        As[a_k + 2][a_row] = av.z;
        As[a_k + 3][a_row] = av.w;

        float4 bv = *(const float4*)(B + (size_t)(k0 + b_k) * NHID + bcol + b_col);
        *(float4*)&Bs[b_k][b_col] = bv;
        __syncthreads();

        #pragma unroll
        for (int kk = 0; kk < BK; kk++) {
            float ar[TM], br[TN];
            #pragma unroll
            for (int i = 0; i < TM; i++) ar[i] = As[kk][ty * TM + i];
            #pragma unroll
            for (int j = 0; j < TN; j++) br[j] = Bs[kk][tx * TN + j];
            #pragma unroll
            for (int i = 0; i < TM; i++)
                #pragma unroll
                for (int j = 0; j < TN; j++)
                    acc[i][j] = fmaf(ar[i], br[j], acc[i][j]);
        }
        __syncthreads();
    }

    #pragma unroll
    for (int i = 0; i < TM; i++) {
        int grow = brow + ty * TM + i;
        if (grow < M) {
            #pragma unroll
            for (int j = 0; j < TN; j += 4) {
                float4 v;
                v.x = fmaxf(acc[i][j + 0], 0.f);
                v.y = fmaxf(acc[i][j + 1], 0.f);
                v.z = fmaxf(acc[i][j + 2], 0.f);
                v.w = fmaxf(acc[i][j + 3], 0.f);
                *(float4*)(C + (size_t)grow * NHID + bcol + tx * TN + j) = v;
            }
        }
    }
}

extern "C" void kernel_launch(void* const* d_in, const int* in_sizes, int n_in,
                              void* d_out, int out_size) {
    const float* x  = nullptr;
    const float* W0 = nullptr;
    const float* W1 = nullptr;
    const void*  ei = nullptr;
    for (int i = 0; i < n_in; i++) {
        long long sz = in_sizes[i];
        if      (sz == (long long)NN * NIN)    x  = (const float*)d_in[i];
        else if (sz == (long long)NIN * NHID)  W0 = (const float*)d_in[i];
        else if (sz == (long long)NHID * NHID) W1 = (const float*)d_in[i];
        else if (sz == (long long)2 * EE)      ei = d_in[i];
    }

    k_detect<<<1, 32>>>(ei);
    k_init <<<(NN + 255) / 256, 256>>>();
    k_count<<<(EE + 255) / 256, 256>>>(ei);
    k_dinv <<<(NN + 255) / 256, 256>>>();
    k_scan1<<<SCAN_NB, SCAN_B>>>();
    k_scan2<<<1, 32>>>();
    k_scan3<<<SCAN_NB, SCAN_B>>>();
    k_fill <<<(EE + 255) / 256, 256>>>(ei);

    k_agg<<<(NN * 32 + 255) / 256, 256>>>(x);

    dim3 gg((NN + BM - 1) / BM, NHID / BN);
    gemm1_relu<NIN><<<gg, 256>>>(W0, NN);                 // g_h  @ W0 -> g_h1
    gemm2_relu<NHID><<<gg, 256>>>(W1, (float*)d_out, NN); // g_h1 @ W1 -> out
}

// round 3
// speedup vs baseline: 2.1444x; 2.1444x over previous
#include <cuda_runtime.h>
#include <cstdint>

// Problem constants
#define NN   50000
#define EE   800000
#define NIN  128
#define NHID 256

#define SCAN_B  1024
#define SCAN_NB ((NN + SCAN_B - 1) / SCAN_B)   // 49

// ---------------- scratch (no allocations allowed) ----------------
__device__ int   g_is64;
__device__ int   g_deg[NN];
__device__ float g_dinv[NN];
__device__ int   g_ptr[NN + 1];
__device__ int   g_cur[NN];
__device__ int   g_src[EE];
__device__ int   g_bsum[SCAN_NB];
__device__ float g_h [(size_t)NN * NIN];    // aggregated features
__device__ float g_h1[(size_t)NN * NHID];   // after layer 1

// ---------------- edge-index dtype detection ----------------
__global__ void k_detect(const void* __restrict__ ei) {
    if (threadIdx.x == 0) {
        const long long* p = (const long long*)ei;
        int ok = 1;
        #pragma unroll
        for (int i = 0; i < 16; i++) {
            long long v = p[i];
            ok &= (v >= 0 && v < NN) ? 1 : 0;
        }
        g_is64 = ok;
    }
}

__device__ __forceinline__ int edge_at(const void* __restrict__ ei, long long idx) {
    if (g_is64) return (int)((const long long*)ei)[idx];
    return ((const int*)ei)[idx];
}

// ---------------- degree / normalization ----------------
__global__ void k_init() {
    int i = blockIdx.x * blockDim.x + threadIdx.x;
    if (i < NN) g_deg[i] = 1;   // self loop
}

__global__ void k_count(const void* __restrict__ ei) {
    int e = blockIdx.x * blockDim.x + threadIdx.x;
    if (e < EE) {
        int col = edge_at(ei, (long long)EE + e);
        atomicAdd(&g_deg[col], 1);
    }
}

__global__ void k_dinv() {
    int i = blockIdx.x * blockDim.x + threadIdx.x;
    if (i < NN) g_dinv[i] = rsqrtf((float)g_deg[i]);
}

// ---------------- exclusive scan of (deg-1) -> CSR row pointers ----------------
__global__ void k_scan1() {
    __shared__ int sh[SCAN_B];
    int gid = blockIdx.x * SCAN_B + threadIdx.x;
    int v = (gid < NN) ? (g_deg[gid] - 1) : 0;
    sh[threadIdx.x] = v;
    __syncthreads();
    for (int off = 1; off < SCAN_B; off <<= 1) {
        int t = (threadIdx.x >= off) ? sh[threadIdx.x - off] : 0;
        __syncthreads();
        sh[threadIdx.x] += t;
        __syncthreads();
    }
    if (gid < NN) g_ptr[gid] = sh[threadIdx.x] - v;   // exclusive within block
    if (threadIdx.x == SCAN_B - 1) g_bsum[blockIdx.x] = sh[SCAN_B - 1];
}

// parallel small scan over SCAN_NB block sums
__global__ void k_scan2() {
    __shared__ int sh[64];
    int t = threadIdx.x;
    sh[t] = (t < SCAN_NB) ? g_bsum[t] : 0;
    __syncthreads();
    if (t < SCAN_NB) {
        int acc = 0;
        #pragma unroll
        for (int b = 0; b < SCAN_NB; b++)
            if (b < t) acc += sh[b];
        g_bsum[t] = acc;
    }
}

__global__ void k_scan3() {
    int gid = blockIdx.x * SCAN_B + threadIdx.x;
    if (gid < NN) {
        int p = g_ptr[gid] + g_bsum[blockIdx.x];
        g_ptr[gid] = p;
        g_cur[gid] = p;
    }
    if (gid == 0) g_ptr[NN] = EE;
}

__global__ void k_fill(const void* __restrict__ ei) {
    int e = blockIdx.x * blockDim.x + threadIdx.x;
    if (e < EE) {
        int row = edge_at(ei, e);
        int col = edge_at(ei, (long long)EE + e);
        int pos = atomicAdd(&g_cur[col], 1);
        g_src[pos] = row;
    }
}

// ---------------- aggregation: warp per target node, gather-only ----------------
__global__ void __launch_bounds__(256) k_agg(const float* __restrict__ x) {
    int w = (blockIdx.x * blockDim.x + threadIdx.x) >> 5;
    int lane = threadIdx.x & 31;
    if (w >= NN) return;
    float di = g_dinv[w];
    const float4* __restrict__ x4 = (const float4*)x;
    float4 a = x4[(size_t)w * 32 + lane];           // self loop
    a.x *= di; a.y *= di; a.z *= di; a.w *= di;
    int s = g_ptr[w], e = g_ptr[w + 1];
    for (int k = s; k < e; k++) {
        int   j  = __ldg(&g_src[k]);
        float wj = __ldg(&g_dinv[j]);
        float4 v = x4[(size_t)j * 32 + lane];
        a.x = fmaf(wj, v.x, a.x);
        a.y = fmaf(wj, v.y, a.y);
        a.z = fmaf(wj, v.z, a.z);
        a.w = fmaf(wj, v.w, a.w);
    }
    a.x *= di; a.y *= di; a.z *= di; a.w *= di;
    ((float4*)g_h)[(size_t)w * 32 + lane] = a;
}

// ---------------- TF32 tensor-core GEMM + ReLU ----------------
// C[M, 256] = relu(A[M, K] @ B[K, 256])
// Block tile 128x128, BK=32. 8 warps in 2(M) x 4(N) grid; warp tile 64x32.
// mma.sync.aligned.m16n8k8.row.col.f32.tf32.tf32.f32

#define GBM 128
#define GBN 128
#define GBK 32
#define ASTR 36     // As row stride (floats): banks (4r + c) mod 32 unique
#define BSTR 136    // Bs row stride (floats): banks (8k + n) mod 32 unique

__device__ __forceinline__ uint32_t f2tf32(float x) {
    uint32_t u;
    asm("cvt.rna.tf32.f32 %0, %1;" : "=r"(u) : "f"(x));
    return u;
}

__device__ __forceinline__ void mma_tf32(float& d0, float& d1, float& d2, float& d3,
                                         uint32_t a0, uint32_t a1, uint32_t a2, uint32_t a3,
                                         uint32_t b0, uint32_t b1) {
    asm volatile(
        "mma.sync.aligned.m16n8k8.row.col.f32.tf32.tf32.f32 "
        "{%0,%1,%2,%3}, {%4,%5,%6,%7}, {%8,%9}, {%0,%1,%2,%3};"
        : "+f"(d0), "+f"(d1), "+f"(d2), "+f"(d3)
        : "r"(a0), "r"(a1), "r"(a2), "r"(a3), "r"(b0), "r"(b1));
}

// LAYER 1: A = g_h (K=128),  C = g_h1
// LAYER 2: A = g_h1 (K=256), C = Cout (d_out)
template<int K, int LAYER>
__global__ void __launch_bounds__(256) gemm_tc(const float* __restrict__ B,
                                               float* __restrict__ Cout, int M) {
    const float* __restrict__ A = (LAYER == 1) ? g_h : g_h1;
    float* __restrict__ C = (LAYER == 1) ? g_h1 : Cout;

    __shared__ uint32_t As[GBM * ASTR];   // [row][k]
    __shared__ uint32_t Bs[GBK * BSTR];   // [k][n]

    int tid  = threadIdx.x;
    int lane = tid & 31;
    int wid  = tid >> 5;
    int wM = (wid >> 2) * 64;   // warp M offset in block: 0 or 64
    int wN = (wid & 3) * 32;    // warp N offset in block: 0,32,64,96

    int brow = blockIdx.x * GBM;
    int bcol = blockIdx.y * GBN;

    float acc[4][4][4];
    #pragma unroll
    for (int mt = 0; mt < 4; mt++)
        #pragma unroll
        for (int nt = 0; nt < 4; nt++)
            #pragma unroll
            for (int r = 0; r < 4; r++) acc[mt][nt][r] = 0.f;

    int r4 = lane >> 2;   // 0..7
    int c4 = lane & 3;    // 0..3

    for (int k0 = 0; k0 < K; k0 += GBK) {
        // load A tile: 128 rows x 32 k = 1024 float4; 4 per thread
        #pragma unroll
        for (int t = 0; t < 4; t++) {
            int idx  = tid + t * 256;        // float4 index
            int row  = idx >> 3;             // 8 float4 per row
            int col  = (idx & 7) * 4;
            int grow = brow + row;
            float4 v = make_float4(0.f, 0.f, 0.f, 0.f);
            if (grow < M) v = *(const float4*)(A + (size_t)grow * K + k0 + col);
            uint32_t* dst = &As[row * ASTR + col];
            dst[0] = f2tf32(v.x); dst[1] = f2tf32(v.y);
            dst[2] = f2tf32(v.z); dst[3] = f2tf32(v.w);
        }
        // load B tile: 32 k x 128 n = 1024 float4; 4 per thread
        #pragma unroll
        for (int t = 0; t < 4; t++) {
            int idx = tid + t * 256;
            int row = idx >> 5;              // 32 float4 per row
            int col = (idx & 31) * 4;
            float4 v = *(const float4*)(B + (size_t)(k0 + row) * NHID + bcol + col);
            uint32_t* dst = &Bs[row * BSTR + col];
            dst[0] = f2tf32(v.x); dst[1] = f2tf32(v.y);
            dst[2] = f2tf32(v.z); dst[3] = f2tf32(v.w);
        }
        __syncthreads();

        #pragma unroll
        for (int kk = 0; kk < GBK; kk += 8) {
            uint32_t af[4][4];
            #pragma unroll
            for (int mt = 0; mt < 4; mt++) {
                int r = wM + mt * 16 + r4;
                int c = kk + c4;
                af[mt][0] = As[r * ASTR + c];
                af[mt][1] = As[(r + 8) * ASTR + c];
                af[mt][2] = As[r * ASTR + c + 4];
                af[mt][3] = As[(r + 8) * ASTR + c + 4];
            }
            uint32_t bf[4][2];
            #pragma unroll
            for (int nt = 0; nt < 4; nt++) {
                int n = wN + nt * 8 + r4;
                int k = kk + c4;
                bf[nt][0] = Bs[k * BSTR + n];
                bf[nt][1] = Bs[(k + 4) * BSTR + n];
            }
            #pragma unroll
            for (int mt = 0; mt < 4; mt++)
                #pragma unroll
                for (int nt = 0; nt < 4; nt++)
                    mma_tf32(acc[mt][nt][0], acc[mt][nt][1], acc[mt][nt][2], acc[mt][nt][3],
                             af[mt][0], af[mt][1], af[mt][2], af[mt][3],
                             bf[nt][0], bf[nt][1]);
        }
        __syncthreads();
    }

    // epilogue: relu + float2 stores
    #pragma unroll
    for (int mt = 0; mt < 4; mt++) {
        int row0 = brow + wM + mt * 16 + r4;
        #pragma unroll
        for (int nt = 0; nt < 4; nt++) {
            int col = bcol + wN + nt * 8 + c4 * 2;
            if (row0 < M) {
                float2 v;
                v.x = fmaxf(acc[mt][nt][0], 0.f);
                v.y = fmaxf(acc[mt][nt][1], 0.f);
                *(float2*)(C + (size_t)row0 * NHID + col) = v;
            }
            if (row0 + 8 < M) {
                float2 v;
                v.x = fmaxf(acc[mt][nt][2], 0.f);
                v.y = fmaxf(acc[mt][nt][3], 0.f);
                *(float2*)(C + (size_t)(row0 + 8) * NHID + col) = v;
            }
        }
    }
}

extern "C" void kernel_launch(void* const* d_in, const int* in_sizes, int n_in,
                              void* d_out, int out_size) {
    const float* x  = nullptr;
    const float* W0 = nullptr;
    const float* W1 = nullptr;
    const void*  ei = nullptr;
    for (int i = 0; i < n_in; i++) {
        long long sz = in_sizes[i];
        if      (sz == (long long)NN * NIN)    x  = (const float*)d_in[i];
        else if (sz == (long long)NIN * NHID)  W0 = (const float*)d_in[i];
        else if (sz == (long long)NHID * NHID) W1 = (const float*)d_in[i];
        else if (sz == (long long)2 * EE)      ei = d_in[i];
    }

    k_detect<<<1, 32>>>(ei);
    k_init <<<(NN + 255) / 256, 256>>>();
    k_count<<<(EE + 255) / 256, 256>>>(ei);
    k_dinv <<<(NN + 255) / 256, 256>>>();
    k_scan1<<<SCAN_NB, SCAN_B>>>();
    k_scan2<<<1, 64>>>();
    k_scan3<<<SCAN_NB, SCAN_B>>>();
    k_fill <<<(EE + 255) / 256, 256>>>(ei);

    k_agg<<<(NN * 32 + 255) / 256, 256>>>(x);

    dim3 gg((NN + GBM - 1) / GBM, NHID / GBN);
    gemm_tc<NIN,  1><<<gg, 256>>>(W0, nullptr, NN);        // g_h  @ W0 -> g_h1
    gemm_tc<NHID, 2><<<gg, 256>>>(W1, (float*)d_out, NN);  // g_h1 @ W1 -> out
}